// round 8
// baseline (speedup 1.0000x reference)
#include <cuda_runtime.h>
#include <math_constants.h>

#define NN       8192
#define IN_DIM   200
#define DD       64
#define BM       128
#define BN       64
#define NT       256
#define STRK     72          // sQ / sK stride (floats): conflict-free frag loads
#define STRV     68          // sV stride (floats): conflict-free with xor swizzle
#define SPLITS   4
#define NEG_BIG  (-1.0e9f)

// Scratch
__device__ float g_H[NN * DD];                 // 2 MB
__device__ float g_Op[SPLITS * NN * DD];       // 8 MB unnormalized partial O
__device__ float g_mp[SPLITS * NN];            // partial row maxes
__device__ float g_lp[SPLITS * NN];            // partial sums

// ---------------------------------------------------------------------------
__device__ __forceinline__ unsigned f2tf32(float f) {
    unsigned r;
    asm("cvt.rna.tf32.f32 %0, %1;" : "=r"(r) : "f"(f));
    return r;
}
__device__ __forceinline__ int perm8(int j) { return ((j & 3) << 1) | (j >> 2); }
__device__ __forceinline__ int perm (int j) { return (j & ~7) | perm8(j & 7); }

__device__ __forceinline__ void mma_tf32(float c[4],
                                         unsigned a0, unsigned a1,
                                         unsigned a2, unsigned a3,
                                         unsigned b0, unsigned b1) {
    asm volatile(
        "mma.sync.aligned.m16n8k8.row.col.f32.tf32.tf32.f32 "
        "{%0,%1,%2,%3}, {%4,%5,%6,%7}, {%8,%9}, {%0,%1,%2,%3};"
        : "+f"(c[0]), "+f"(c[1]), "+f"(c[2]), "+f"(c[3])
        : "r"(a0), "r"(a1), "r"(a2), "r"(a3), "r"(b0), "r"(b1));
}

// ---------------------------------------------------------------------------
// Kernel 1: H = X @ W + b.  16 rows/block, 4 rows/thread (ILP 4, 4x W reuse).
// ---------------------------------------------------------------------------
__global__ void h_kernel(const float* __restrict__ X,
                         const float* __restrict__ W,
                         const float* __restrict__ b) {
    __shared__ float sx[16 * IN_DIM];
    const int tid  = threadIdx.x;
    const int rowq = blockIdx.x * 16;
    for (int i = tid; i < 16 * IN_DIM; i += 256)
        sx[i] = X[(size_t)rowq * IN_DIM + i];
    __syncthreads();
    const int r = tid >> 6, d = tid & 63;
    const float* x0 = sx + r * IN_DIM;
    const float* x1 = sx + (r + 4) * IN_DIM;
    const float* x2 = sx + (r + 8) * IN_DIM;
    const float* x3 = sx + (r + 12) * IN_DIM;
    float a0 = b[d], a1 = a0, a2 = a0, a3 = a0;
#pragma unroll 8
    for (int k = 0; k < IN_DIM; k++) {
        float wv = W[k * DD + d];
        a0 = fmaf(x0[k], wv, a0);
        a1 = fmaf(x1[k], wv, a1);
        a2 = fmaf(x2[k], wv, a2);
        a3 = fmaf(x3[k], wv, a3);
    }
    g_H[(rowq + r) * DD + d]      = a0;
    g_H[(rowq + r + 4) * DD + d]  = a1;
    g_H[(rowq + r + 8) * DD + d]  = a2;
    g_H[(rowq + r + 12) * DD + d] = a3;
}

// ---------------------------------------------------------------------------
// Kernel 2: split-K flash attention, online softmax, software-pipelined:
// double-buffered sK/sV/sAb, register prefetch 1 tile ahead, 1 barrier/tile.
// ---------------------------------------------------------------------------
__global__ __launch_bounds__(NT, 2)
void flash_mma(const int* __restrict__ A) {
    extern __shared__ float sm[];
    float*    sQ  = sm;                         // [128][STRK] A-frag layout
    float*    sKb = sQ + BM * STRK;             // 2 x [64][STRK]
    float*    sVb = sKb + 2 * BN * STRK;        // 2 x [64][STRV]
    unsigned* sAb = (unsigned*)(sVb + 2 * DD * STRV);  // 2 x [256]

    const int tid   = threadIdx.x;
    const int lane  = tid & 31;
    const int w     = tid >> 5;               // 0..7
    const int lr    = lane >> 2;              // 0..7
    const int lc    = lane & 3;               // 0..3
    const int split = blockIdx.x >> 6;        // 0..3
    const int qt    = blockIdx.x & 63;
    const int qbase = qt * BM;
    const int t0    = split * 32;
    const int t1    = t0 + 32;

    const int lrow0 = w * 16 + lr;            // CTA-local row
    const int r0    = qbase + lrow0;

    // staging index maps (fixed per thread)
    const int skey[4] = { (tid + 0*NT) >> 4, (tid + 1*NT) >> 4,
                          (tid + 2*NT) >> 4, (tid + 3*NT) >> 4 };
    const int sd4 = (tid & 15) * 4;
    const int arow  = tid >> 1;               // 0..127
    const int ahalf = tid & 1;
    const int* aptr = A + (size_t)(qbase + arow) * NN + ahalf * 32;

    // ---- stage Q tile into smem (fragment layout, tf32) ----
#pragma unroll
    for (int ii = 0; ii < 8; ii++) {
        int i   = tid + ii * NT;              // float4 index over 128x64
        int row = i >> 4;
        int d4  = (i & 15) * 4;
        float4 v = *(const float4*)&g_H[(size_t)(qbase + row) * DD + d4];
        sQ[row * STRK + perm(d4)    ] = __uint_as_float(f2tf32(v.x));
        sQ[row * STRK + perm(d4 + 1)] = __uint_as_float(f2tf32(v.y));
        sQ[row * STRK + perm(d4 + 2)] = __uint_as_float(f2tf32(v.z));
        sQ[row * STRK + perm(d4 + 3)] = __uint_as_float(f2tf32(v.w));
    }

    // ---- prologue: stage tile t0 directly; prefetch t0+1 into registers ----
#pragma unroll
    for (int ii = 0; ii < 4; ii++) {
        int key = skey[ii], d4 = sd4;
        float4 v = *(const float4*)&g_H[(size_t)(t0 * BN + key) * DD + d4];
        int kp   = perm(key);
        int krow = (key & ~7) | perm8(key & 7);
        sKb[krow * STRK + perm(d4)    ] = __uint_as_float(f2tf32(v.x));
        sKb[krow * STRK + perm(d4 + 1)] = __uint_as_float(f2tf32(v.y));
        sKb[krow * STRK + perm(d4 + 2)] = __uint_as_float(f2tf32(v.z));
        sKb[krow * STRK + perm(d4 + 3)] = __uint_as_float(f2tf32(v.w));
        sVb[(d4    ) * STRV + (kp ^ (((d4    ) & 7) << 3))] = __uint_as_float(f2tf32(v.x));
        sVb[(d4 + 1) * STRV + (kp ^ (((d4 + 1) & 7) << 3))] = __uint_as_float(f2tf32(v.y));
        sVb[(d4 + 2) * STRV + (kp ^ (((d4 + 2) & 7) << 3))] = __uint_as_float(f2tf32(v.z));
        sVb[(d4 + 3) * STRV + (kp ^ (((d4 + 3) & 7) << 3))] = __uint_as_float(f2tf32(v.w));
    }
    {   // A(t0) load + pack + store
        const int4* p = (const int4*)(aptr + t0 * BN);
        unsigned bbits = 0;
#pragma unroll
        for (int j = 0; j < 8; j++) {
            int4 v = p[j];
            bbits |= (v.x > 0 ? 1u << (4 * j)     : 0u)
                   | (v.y > 0 ? 1u << (4 * j + 1) : 0u)
                   | (v.z > 0 ? 1u << (4 * j + 2) : 0u)
                   | (v.w > 0 ? 1u << (4 * j + 3) : 0u);
        }
        sAb[arow * 2 + ahalf] = bbits;
    }
    // register prefetch of tile t0+1 (raw)
    float4 kv[4];
    int4   av[8];
#pragma unroll
    for (int ii = 0; ii < 4; ii++)
        kv[ii] = *(const float4*)&g_H[(size_t)((t0 + 1) * BN + skey[ii]) * DD + sd4];
#pragma unroll
    for (int j = 0; j < 8; j++)
        av[j] = ((const int4*)(aptr + (t0 + 1) * BN))[j];

    float oc[8][4];
#pragma unroll
    for (int na = 0; na < 8; na++)
#pragma unroll
        for (int j = 0; j < 4; j++) oc[na][j] = 0.0f;
    float m0 = -CUDART_INF_F, m1 = -CUDART_INF_F;
    float l0 = 0.0f, l1 = 0.0f;

    __syncthreads();

    for (int t = t0; t < t1; t++) {
        const int b = (t - t0) & 1;
        float* sK = sKb + (b ^ 1) * BN * STRK;   // write side
        float* sV = sVb + (b ^ 1) * DD * STRV;

        // ---- store prefetched tile t+1 (cvt + STS); data arrived last tile ----
        if (t + 1 < t1) {
#pragma unroll
            for (int ii = 0; ii < 4; ii++) {
                int key = skey[ii], d4 = sd4;
                float4 v = kv[ii];
                float tt0 = __uint_as_float(f2tf32(v.x));
                float tt1 = __uint_as_float(f2tf32(v.y));
                float tt2 = __uint_as_float(f2tf32(v.z));
                float tt3 = __uint_as_float(f2tf32(v.w));
                int kp   = perm(key);
                int krow = (key & ~7) | perm8(key & 7);
                sK[krow * STRK + perm(d4)    ] = tt0;
                sK[krow * STRK + perm(d4 + 1)] = tt1;
                sK[krow * STRK + perm(d4 + 2)] = tt2;
                sK[krow * STRK + perm(d4 + 3)] = tt3;
                sV[(d4    ) * STRV + (kp ^ (((d4    ) & 7) << 3))] = tt0;
                sV[(d4 + 1) * STRV + (kp ^ (((d4 + 1) & 7) << 3))] = tt1;
                sV[(d4 + 2) * STRV + (kp ^ (((d4 + 2) & 7) << 3))] = tt2;
                sV[(d4 + 3) * STRV + (kp ^ (((d4 + 3) & 7) << 3))] = tt3;
            }
            unsigned bbits = 0;
#pragma unroll
            for (int j = 0; j < 8; j++) {
                int4 v = av[j];
                bbits |= (v.x > 0 ? 1u << (4 * j)     : 0u)
                       | (v.y > 0 ? 1u << (4 * j + 1) : 0u)
                       | (v.z > 0 ? 1u << (4 * j + 2) : 0u)
                       | (v.w > 0 ? 1u << (4 * j + 3) : 0u);
            }
            sAb[(b ^ 1) * 256 + arow * 2 + ahalf] = bbits;
        }
        // ---- issue LDGs for tile t+2 (consumed next iteration) ----
        if (t + 2 < t1) {
#pragma unroll
            for (int ii = 0; ii < 4; ii++)
                kv[ii] = *(const float4*)&g_H[(size_t)((t + 2) * BN + skey[ii]) * DD + sd4];
#pragma unroll
            for (int j = 0; j < 8; j++)
                av[j] = ((const int4*)(aptr + (t + 2) * BN))[j];
        }

        // ---- compute tile t from buffer b ----
        const float* cK = sKb + b * BN * STRK;
        const float* cV = sVb + b * DD * STRV;

        float sc[8][4];
#pragma unroll
        for (int na = 0; na < 8; na++)
#pragma unroll
            for (int j = 0; j < 4; j++) sc[na][j] = 0.0f;
#pragma unroll
        for (int ks = 0; ks < 8; ks++) {
            float2 qa = *(const float2*)&sQ[lrow0 * STRK + ks * 8 + 2 * lc];
            float2 qb = *(const float2*)&sQ[(lrow0 + 8) * STRK + ks * 8 + 2 * lc];
            unsigned a0 = __float_as_uint(qa.x);
            unsigned a1 = __float_as_uint(qb.x);
            unsigned a2 = __float_as_uint(qa.y);
            unsigned a3 = __float_as_uint(qb.y);
#pragma unroll
            for (int na = 0; na < 8; na++) {
                float2 bf = *(const float2*)&cK[(na * 8 + lr) * STRK + ks * 8 + 2 * lc];
                mma_tf32(sc[na], a0, a1, a2, a3,
                         __float_as_uint(bf.x), __float_as_uint(bf.y));
            }
        }

        // ---- mask to NEG_BIG ----
        {
            unsigned b0w0 = sAb[b * 256 + lrow0 * 2];
            unsigned b0w1 = sAb[b * 256 + lrow0 * 2 + 1];
            unsigned b1w0 = sAb[b * 256 + (lrow0 + 8) * 2];
            unsigned b1w1 = sAb[b * 256 + (lrow0 + 8) * 2 + 1];
#pragma unroll
            for (int na = 0; na < 8; na++) {
                unsigned m0w = (na < 4) ? b0w0 : b0w1;
                unsigned m1w = (na < 4) ? b1w0 : b1w1;
                int sh = ((na & 3) << 3) + lc;
                sc[na][0] = ((m0w >> sh)       & 1) ? sc[na][0] : NEG_BIG;
                sc[na][1] = ((m0w >> (sh + 4)) & 1) ? sc[na][1] : NEG_BIG;
                sc[na][2] = ((m1w >> sh)       & 1) ? sc[na][2] : NEG_BIG;
                sc[na][3] = ((m1w >> (sh + 4)) & 1) ? sc[na][3] : NEG_BIG;
            }
        }

        // ---- online softmax; sc becomes the P A-fragments in place ----
        {
            float mt0 = NEG_BIG, mt1 = NEG_BIG;
#pragma unroll
            for (int na = 0; na < 8; na++) {
                mt0 = fmaxf(mt0, fmaxf(sc[na][0], sc[na][1]));
                mt1 = fmaxf(mt1, fmaxf(sc[na][2], sc[na][3]));
            }
            mt0 = fmaxf(mt0, __shfl_xor_sync(0xffffffffu, mt0, 1));
            mt0 = fmaxf(mt0, __shfl_xor_sync(0xffffffffu, mt0, 2));
            mt1 = fmaxf(mt1, __shfl_xor_sync(0xffffffffu, mt1, 1));
            mt1 = fmaxf(mt1, __shfl_xor_sync(0xffffffffu, mt1, 2));

            float mn0 = fmaxf(m0, mt0), mn1 = fmaxf(m1, mt1);
            float scl0 = __expf(m0 - mn0), scl1 = __expf(m1 - mn1);
            m0 = mn0; m1 = mn1;

            float s0 = 0.0f, s1 = 0.0f;
#pragma unroll
            for (int na = 0; na < 8; na++) {
                float p00 = __expf(sc[na][0] - m0);
                float p01 = __expf(sc[na][1] - m0);
                float p10 = __expf(sc[na][2] - m1);
                float p11 = __expf(sc[na][3] - m1);
                s0 += p00 + p01;
                s1 += p10 + p11;
                sc[na][0] = __uint_as_float(f2tf32(p00));
                sc[na][1] = __uint_as_float(f2tf32(p01));
                sc[na][2] = __uint_as_float(f2tf32(p10));
                sc[na][3] = __uint_as_float(f2tf32(p11));
            }
            s0 += __shfl_xor_sync(0xffffffffu, s0, 1);
            s0 += __shfl_xor_sync(0xffffffffu, s0, 2);
            s1 += __shfl_xor_sync(0xffffffffu, s1, 1);
            s1 += __shfl_xor_sync(0xffffffffu, s1, 2);
            l0 = l0 * scl0 + s0;
            l1 = l1 * scl1 + s1;

#pragma unroll
            for (int na = 0; na < 8; na++) {
                oc[na][0] *= scl0; oc[na][1] *= scl0;
                oc[na][2] *= scl1; oc[na][3] *= scl1;
            }
        }

        // ---- O += P V (P direct from registers) ----
#pragma unroll
        for (int ks = 0; ks < 8; ks++) {
            unsigned a0 = __float_as_uint(sc[ks][0]);   // (lr,   k)
            unsigned a1 = __float_as_uint(sc[ks][2]);   // (lr+8, k)
            unsigned a2 = __float_as_uint(sc[ks][1]);   // (lr,   k+4)
            unsigned a3 = __float_as_uint(sc[ks][3]);   // (lr+8, k+4)
#pragma unroll
            for (int na = 0; na < 8; na++) {
                float2 bf = *(const float2*)&cV[(na * 8 + lr) * STRV + (((ks ^ lr) << 3) + 2 * lc)];
                mma_tf32(oc[na], a0, a1, a2, a3,
                         __float_as_uint(bf.x), __float_as_uint(bf.y));
            }
        }

        __syncthreads();   // buffer b free for rewrite; b^1 writes published
    }

    // ---- write partials ----
    float* Op = g_Op + (size_t)split * NN * DD;
#pragma unroll
    for (int na = 0; na < 8; na++) {
        int c0 = na * 8 + 2 * lc;
        *(float2*)&Op[(size_t)r0 * DD + c0]       = make_float2(oc[na][0], oc[na][1]);
        *(float2*)&Op[(size_t)(r0 + 8) * DD + c0] = make_float2(oc[na][2], oc[na][3]);
    }
    if (lc == 0) {
        g_mp[split * NN + r0]     = m0;
        g_mp[split * NN + r0 + 8] = m1;
        g_lp[split * NN + r0]     = l0;
        g_lp[split * NN + r0 + 8] = l1;
    }
}

// ---------------------------------------------------------------------------
// Kernel 3: m-aware merge of the 4 split partials, normalize, relu.
// ---------------------------------------------------------------------------
__global__ void merge_kernel(float* __restrict__ Out) {
    int idx = blockIdx.x * 256 + threadIdx.x;      // over NN*DD
    int row = idx >> 6;
    float ma = g_mp[row], mb = g_mp[NN + row];
    float mc = g_mp[2 * NN + row], md = g_mp[3 * NN + row];
    float M = fmaxf(fmaxf(ma, mb), fmaxf(mc, md));
    float w0 = __expf(ma - M), w1 = __expf(mb - M);
    float w2 = __expf(mc - M), w3 = __expf(md - M);
    float denom = w0 * g_lp[row] + w1 * g_lp[NN + row]
                + w2 * g_lp[2 * NN + row] + w3 * g_lp[3 * NN + row];
    float num = w0 * g_Op[idx] + w1 * g_Op[NN * DD + idx]
              + w2 * g_Op[2 * NN * DD + idx] + w3 * g_Op[3 * NN * DD + idx];
    Out[idx] = fmaxf(num / denom, 0.0f);
}

// ---------------------------------------------------------------------------
extern "C" void kernel_launch(void* const* d_in, const int* in_sizes, int n_in,
                              void* d_out, int out_size) {
    const float* X = (const float*)d_in[0];
    const int*   A = (const int*)  d_in[1];
    const float* W = (const float*)d_in[2];
    const float* b = (const float*)d_in[3];
    float* Out = (float*)d_out;

    const int smem_bytes = (BM * STRK + 2 * BN * STRK + 2 * DD * STRV) * 4
                         + 2 * 256 * 4;   // 36864+36864+34816+2048 = 110592
    static bool attr_set = false;
    if (!attr_set) {
        cudaFuncSetAttribute(flash_mma,
                             cudaFuncAttributeMaxDynamicSharedMemorySize,
                             smem_bytes);
        attr_set = true;
    }

    h_kernel<<<NN / 16, 256>>>(X, W, b);
    flash_mma<<<SPLITS * 64, NT, smem_bytes>>>(A);
    merge_kernel<<<NN * DD / 256, 256>>>(Out);
}

// round 9
// speedup vs baseline: 1.4422x; 1.4422x over previous
#include <cuda_runtime.h>
#include <math_constants.h>

#define NN       8192
#define IN_DIM   200
#define DD       64
#define BM       128
#define BN       64
#define NT       256
#define STRK     72          // sQ / sK stride (floats); 288 B = 16B multiple
#define STRV     68          // sV stride (floats);  272 B = 16B multiple
#define SPLITS   4
#define NEG_BIG  (-1.0e9f)

// Scratch (all __device__ globals; no allocations)
__device__ float    g_Hq[NN * DD];             // Q layout: [row][perm(d)]           tf32
__device__ float    g_Hk[NN * DD];             // K layout: [tile][krow][perm(d)]    tf32
__device__ float    g_Hv[NN * DD];             // V layout: [tile][d][perm(key)^swz] tf32
__device__ unsigned g_Ab[NN * (NN / 32)];      // adjacency bitmask, bit i <-> key i
__device__ float    g_Op[SPLITS * NN * DD];    // unnormalized partial O
__device__ float    g_mp[SPLITS * NN];
__device__ float    g_lp[SPLITS * NN];

// ---------------------------------------------------------------------------
__device__ __forceinline__ unsigned f2tf32(float f) {
    unsigned r;
    asm("cvt.rna.tf32.f32 %0, %1;" : "=r"(r) : "f"(f));
    return r;
}
__device__ __forceinline__ int perm8(int j) { return ((j & 3) << 1) | (j >> 2); }
__device__ __forceinline__ int perm (int j) { return (j & ~7) | perm8(j & 7); }

__device__ __forceinline__ void mma_tf32(float c[4],
                                         unsigned a0, unsigned a1,
                                         unsigned a2, unsigned a3,
                                         unsigned b0, unsigned b1) {
    asm volatile(
        "mma.sync.aligned.m16n8k8.row.col.f32.tf32.tf32.f32 "
        "{%0,%1,%2,%3}, {%4,%5,%6,%7}, {%8,%9}, {%0,%1,%2,%3};"
        : "+f"(c[0]), "+f"(c[1]), "+f"(c[2]), "+f"(c[3])
        : "r"(a0), "r"(a1), "r"(a2), "r"(a3), "r"(b0), "r"(b1));
}

__device__ __forceinline__ void cpa16(unsigned d, const void* s) {
    asm volatile("cp.async.cg.shared.global [%0], [%1], 16;" :: "r"(d), "l"(s));
}
__device__ __forceinline__ void cpa8(unsigned d, const void* s) {
    asm volatile("cp.async.ca.shared.global [%0], [%1], 8;" :: "r"(d), "l"(s));
}
__device__ __forceinline__ void cpa_commit() {
    asm volatile("cp.async.commit_group;" ::: "memory");
}
template <int N>
__device__ __forceinline__ void cpa_wait() {
    asm volatile("cp.async.wait_group %0;" :: "n"(N) : "memory");
}

// ---------------------------------------------------------------------------
// Kernel 1: H = X @ W + b, written tf32-rounded into all three flash layouts.
// ---------------------------------------------------------------------------
__global__ void h_kernel(const float* __restrict__ X,
                         const float* __restrict__ W,
                         const float* __restrict__ b) {
    __shared__ float sx[8 * IN_DIM];
    const int tid  = threadIdx.x;
    const int rowq = blockIdx.x * 8;
    for (int i = tid; i < 8 * IN_DIM; i += 256)
        sx[i] = X[(size_t)rowq * IN_DIM + i];
    __syncthreads();
    const int r = tid >> 6, d = tid & 63;
    const float* x0 = sx + r * IN_DIM;
    const float* x1 = sx + (r + 4) * IN_DIM;
    float acc0 = b[d], acc1 = acc0;
#pragma unroll 8
    for (int k = 0; k < IN_DIM; k++) {
        float wv = W[k * DD + d];
        acc0 = fmaf(x0[k], wv, acc0);
        acc1 = fmaf(x1[k], wv, acc1);
    }
    const int pd = perm(d);
#pragma unroll
    for (int rr = 0; rr < 2; rr++) {
        int   row = rowq + r + rr * 4;
        float val = __uint_as_float(f2tf32(rr ? acc1 : acc0));
        int   t   = row >> 6, key = row & 63;
        int   krow = (key & ~7) | perm8(key & 7);
        g_Hq[row * DD + pd] = val;
        g_Hk[t * (BN * DD) + krow * DD + pd] = val;
        g_Hv[t * (BN * DD) + d * DD + (perm(key) ^ ((d & 7) << 3))] = val;
    }
}

// ---------------------------------------------------------------------------
// Kernel 1b: pack adjacency into bitmask (the mandatory 268 MB DRAM stream,
// run as a pure streaming kernel at full bandwidth).
// ---------------------------------------------------------------------------
__global__ void apack_kernel(const int* __restrict__ A) {
    const int row  = blockIdx.x;
    const int word = threadIdx.x;                 // 256 words of 32 keys
    const int4* p  = (const int4*)(A + (size_t)row * NN + word * 32);
    unsigned bits = 0;
#pragma unroll
    for (int j = 0; j < 8; j++) {
        int4 v = p[j];
        bits |= (v.x > 0 ? 1u << (4 * j)     : 0u)
              | (v.y > 0 ? 1u << (4 * j + 1) : 0u)
              | (v.z > 0 ? 1u << (4 * j + 2) : 0u)
              | (v.w > 0 ? 1u << (4 * j + 3) : 0u);
    }
    g_Ab[row * 256 + word] = bits;
}

// ---------------------------------------------------------------------------
// Kernel 2: split-K flash attention; cp.async double-buffered staging
// (zero register cost), online softmax, P stays in registers.
// ---------------------------------------------------------------------------
__global__ __launch_bounds__(NT, 2)
void flash_mma() {
    extern __shared__ float sm[];
    float*    sQ  = sm;                          // [128][STRK]
    float*    sKb = sQ + BM * STRK;              // 2 x [64][STRK]
    float*    sVb = sKb + 2 * BN * STRK;         // 2 x [64][STRV]
    unsigned* sAb = (unsigned*)(sVb + 2 * DD * STRV);   // 2 x [256] words

    const unsigned smb    = (unsigned)__cvta_generic_to_shared(sm);
    const unsigned smbK   = smb + BM * STRK * 4;
    const unsigned smbV   = smbK + 2 * BN * STRK * 4;
    const unsigned smbA   = smbV + 2 * DD * STRV * 4;
    const unsigned KBYTES = BN * STRK * 4;
    const unsigned VBYTES = DD * STRV * 4;

    const int tid   = threadIdx.x;
    const int lane  = tid & 31;
    const int w     = tid >> 5;
    const int lr    = lane >> 2;
    const int lc    = lane & 3;
    const int split = blockIdx.x >> 6;           // 0..3
    const int qt    = blockIdx.x & 63;
    const int qbase = qt * BM;
    const int t0    = split * 32;
    const int t1    = t0 + 32;

    const int lrow0 = w * 16 + lr;
    const int r0    = qbase + lrow0;

    // staging chunk map (fixed): chunk c covers row c>>4, floats (c&15)*4..+3
    const int srow = tid >> 4;
    const int sj4  = (tid & 15) * 4;

    // ---- prologue: group0 = Q + tile t0(stage0); group1 = tile t0+1(stage1) ----
#pragma unroll
    for (int ii = 0; ii < 8; ii++) {
        int c = tid + ii * NT;                   // 2048 chunks over 128x64
        int row = c >> 4, j4 = (c & 15) * 4;
        cpa16(smb + (row * STRK + j4) * 4,
              &g_Hq[(size_t)(qbase + row) * DD + j4]);
    }
    {
        const float* gk = &g_Hk[(size_t)t0 * BN * DD];
        const float* gv = &g_Hv[(size_t)t0 * BN * DD];
#pragma unroll
        for (int ii = 0; ii < 4; ii++) {
            int c = tid + ii * NT;
            int row = c >> 4, j4 = (c & 15) * 4;
            cpa16(smbK + (row * STRK + j4) * 4, gk + row * DD + j4);
            cpa16(smbV + (row * STRV + j4) * 4, gv + row * DD + j4);
        }
        if (tid < BM)
            cpa8(smbA + tid * 8, &g_Ab[(size_t)(qbase + tid) * 256 + t0 * 2]);
    }
    cpa_commit();
    {
        const float* gk = &g_Hk[(size_t)(t0 + 1) * BN * DD];
        const float* gv = &g_Hv[(size_t)(t0 + 1) * BN * DD];
#pragma unroll
        for (int ii = 0; ii < 4; ii++) {
            int c = tid + ii * NT;
            int row = c >> 4, j4 = (c & 15) * 4;
            cpa16(smbK + KBYTES + (row * STRK + j4) * 4, gk + row * DD + j4);
            cpa16(smbV + VBYTES + (row * STRV + j4) * 4, gv + row * DD + j4);
        }
        if (tid < BM)
            cpa8(smbA + 1024 + tid * 8, &g_Ab[(size_t)(qbase + tid) * 256 + (t0 + 1) * 2]);
    }
    cpa_commit();

    float oc[8][4];
#pragma unroll
    for (int na = 0; na < 8; na++)
#pragma unroll
        for (int j = 0; j < 4; j++) oc[na][j] = 0.0f;
    float m0 = -CUDART_INF_F, m1 = -CUDART_INF_F;
    float l0 = 0.0f, l1 = 0.0f;

    cpa_wait<1>();          // group0 (Q + tile t0) complete
    __syncthreads();

    for (int t = t0; t < t1; t++) {
        const int b = (t - t0) & 1;
        const float* cK = sKb + b * BN * STRK;
        const float* cV = sVb + b * DD * STRV;

        // ---- S = Q K^T ----
        float sc[8][4];
#pragma unroll
        for (int na = 0; na < 8; na++)
#pragma unroll
            for (int j = 0; j < 4; j++) sc[na][j] = 0.0f;
#pragma unroll
        for (int ks = 0; ks < 8; ks++) {
            float2 qa = *(const float2*)&sQ[lrow0 * STRK + ks * 8 + 2 * lc];
            float2 qb = *(const float2*)&sQ[(lrow0 + 8) * STRK + ks * 8 + 2 * lc];
            unsigned a0 = __float_as_uint(qa.x);
            unsigned a1 = __float_as_uint(qb.x);
            unsigned a2 = __float_as_uint(qa.y);
            unsigned a3 = __float_as_uint(qb.y);
#pragma unroll
            for (int na = 0; na < 8; na++) {
                float2 bf = *(const float2*)&cK[(na * 8 + lr) * STRK + ks * 8 + 2 * lc];
                mma_tf32(sc[na], a0, a1, a2, a3,
                         __float_as_uint(bf.x), __float_as_uint(bf.y));
            }
        }

        // ---- mask to NEG_BIG (bitmask words from smem) ----
        {
            unsigned b0w0 = sAb[b * 256 + lrow0 * 2];
            unsigned b0w1 = sAb[b * 256 + lrow0 * 2 + 1];
            unsigned b1w0 = sAb[b * 256 + (lrow0 + 8) * 2];
            unsigned b1w1 = sAb[b * 256 + (lrow0 + 8) * 2 + 1];
#pragma unroll
            for (int na = 0; na < 8; na++) {
                unsigned m0w = (na < 4) ? b0w0 : b0w1;
                unsigned m1w = (na < 4) ? b1w0 : b1w1;
                int sh = ((na & 3) << 3) + lc;
                sc[na][0] = ((m0w >> sh)       & 1) ? sc[na][0] : NEG_BIG;
                sc[na][1] = ((m0w >> (sh + 4)) & 1) ? sc[na][1] : NEG_BIG;
                sc[na][2] = ((m1w >> sh)       & 1) ? sc[na][2] : NEG_BIG;
                sc[na][3] = ((m1w >> (sh + 4)) & 1) ? sc[na][3] : NEG_BIG;
            }
        }

        // ---- online softmax; sc becomes the P A-fragments in place ----
        {
            float mt0 = NEG_BIG, mt1 = NEG_BIG;
#pragma unroll
            for (int na = 0; na < 8; na++) {
                mt0 = fmaxf(mt0, fmaxf(sc[na][0], sc[na][1]));
                mt1 = fmaxf(mt1, fmaxf(sc[na][2], sc[na][3]));
            }
            mt0 = fmaxf(mt0, __shfl_xor_sync(0xffffffffu, mt0, 1));
            mt0 = fmaxf(mt0, __shfl_xor_sync(0xffffffffu, mt0, 2));
            mt1 = fmaxf(mt1, __shfl_xor_sync(0xffffffffu, mt1, 1));
            mt1 = fmaxf(mt1, __shfl_xor_sync(0xffffffffu, mt1, 2));

            float mn0 = fmaxf(m0, mt0), mn1 = fmaxf(m1, mt1);
            float scl0 = __expf(m0 - mn0), scl1 = __expf(m1 - mn1);
            m0 = mn0; m1 = mn1;

            float s0 = 0.0f, s1 = 0.0f;
#pragma unroll
            for (int na = 0; na < 8; na++) {
                float p00 = __expf(sc[na][0] - m0);
                float p01 = __expf(sc[na][1] - m0);
                float p10 = __expf(sc[na][2] - m1);
                float p11 = __expf(sc[na][3] - m1);
                s0 += p00 + p01;
                s1 += p10 + p11;
                sc[na][0] = __uint_as_float(f2tf32(p00));
                sc[na][1] = __uint_as_float(f2tf32(p01));
                sc[na][2] = __uint_as_float(f2tf32(p10));
                sc[na][3] = __uint_as_float(f2tf32(p11));
            }
            s0 += __shfl_xor_sync(0xffffffffu, s0, 1);
            s0 += __shfl_xor_sync(0xffffffffu, s0, 2);
            s1 += __shfl_xor_sync(0xffffffffu, s1, 1);
            s1 += __shfl_xor_sync(0xffffffffu, s1, 2);
            l0 = l0 * scl0 + s0;
            l1 = l1 * scl1 + s1;

#pragma unroll
            for (int na = 0; na < 8; na++) {
                oc[na][0] *= scl0; oc[na][1] *= scl0;
                oc[na][2] *= scl1; oc[na][3] *= scl1;
            }
        }

        // ---- O += P V ----
#pragma unroll
        for (int ks = 0; ks < 8; ks++) {
            unsigned a0 = __float_as_uint(sc[ks][0]);
            unsigned a1 = __float_as_uint(sc[ks][2]);
            unsigned a2 = __float_as_uint(sc[ks][1]);
            unsigned a3 = __float_as_uint(sc[ks][3]);
#pragma unroll
            for (int na = 0; na < 8; na++) {
                float2 bf = *(const float2*)&cV[(na * 8 + lr) * STRV + (((ks ^ lr) << 3) + 2 * lc)];
                mma_tf32(oc[na], a0, a1, a2, a3,
                         __float_as_uint(bf.x), __float_as_uint(bf.y));
            }
        }

        __syncthreads();              // all reads of stage b finished
        if (t + 2 < t1) {             // refill stage b with tile t+2
            const float* gk = &g_Hk[(size_t)(t + 2) * BN * DD];
            const float* gv = &g_Hv[(size_t)(t + 2) * BN * DD];
            cpa16(smbK + b * KBYTES + (srow * STRK + sj4) * 4, gk + srow * DD + sj4);
            cpa16(smbK + b * KBYTES + ((srow + 16) * STRK + sj4) * 4, gk + (srow + 16) * DD + sj4);
            cpa16(smbK + b * KBYTES + ((srow + 32) * STRK + sj4) * 4, gk + (srow + 32) * DD + sj4);
            cpa16(smbK + b * KBYTES + ((srow + 48) * STRK + sj4) * 4, gk + (srow + 48) * DD + sj4);
            cpa16(smbV + b * VBYTES + (srow * STRV + sj4) * 4, gv + srow * DD + sj4);
            cpa16(smbV + b * VBYTES + ((srow + 16) * STRV + sj4) * 4, gv + (srow + 16) * DD + sj4);
            cpa16(smbV + b * VBYTES + ((srow + 32) * STRV + sj4) * 4, gv + (srow + 32) * DD + sj4);
            cpa16(smbV + b * VBYTES + ((srow + 48) * STRV + sj4) * 4, gv + (srow + 48) * DD + sj4);
            if (tid < BM)
                cpa8(smbA + b * 1024 + tid * 8,
                     &g_Ab[(size_t)(qbase + tid) * 256 + (t + 2) * 2]);
            cpa_commit();
            cpa_wait<1>();            // tile t+1 (older group) complete
        } else {
            cpa_wait<0>();            // drain: tile t+1 complete
        }
        __syncthreads();              // t+1 data published to all threads
    }

    // ---- write partials ----
    float* Op = g_Op + (size_t)split * NN * DD;
#pragma unroll
    for (int na = 0; na < 8; na++) {
        int c0 = na * 8 + 2 * lc;
        *(float2*)&Op[(size_t)r0 * DD + c0]       = make_float2(oc[na][0], oc[na][1]);
        *(float2*)&Op[(size_t)(r0 + 8) * DD + c0] = make_float2(oc[na][2], oc[na][3]);
    }
    if (lc == 0) {
        g_mp[split * NN + r0]     = m0;
        g_mp[split * NN + r0 + 8] = m1;
        g_lp[split * NN + r0]     = l0;
        g_lp[split * NN + r0 + 8] = l1;
    }
}

// ---------------------------------------------------------------------------
// Kernel 3: m-aware merge, normalize, relu.
// ---------------------------------------------------------------------------
__global__ void merge_kernel(float* __restrict__ Out) {
    int idx = blockIdx.x * 256 + threadIdx.x;
    int row = idx >> 6;
    float ma = g_mp[row], mb = g_mp[NN + row];
    float mc = g_mp[2 * NN + row], md = g_mp[3 * NN + row];
    float M = fmaxf(fmaxf(ma, mb), fmaxf(mc, md));
    float w0 = __expf(ma - M), w1 = __expf(mb - M);
    float w2 = __expf(mc - M), w3 = __expf(md - M);
    float denom = w0 * g_lp[row] + w1 * g_lp[NN + row]
                + w2 * g_lp[2 * NN + row] + w3 * g_lp[3 * NN + row];
    float num = w0 * g_Op[idx] + w1 * g_Op[NN * DD + idx]
              + w2 * g_Op[2 * NN * DD + idx] + w3 * g_Op[3 * NN * DD + idx];
    Out[idx] = fmaxf(num / denom, 0.0f);
}

// ---------------------------------------------------------------------------
extern "C" void kernel_launch(void* const* d_in, const int* in_sizes, int n_in,
                              void* d_out, int out_size) {
    const float* X = (const float*)d_in[0];
    const int*   A = (const int*)  d_in[1];
    const float* W = (const float*)d_in[2];
    const float* b = (const float*)d_in[3];
    float* Out = (float*)d_out;

    const int smem_bytes = (BM * STRK + 2 * BN * STRK + 2 * DD * STRV) * 4
                         + 2 * 256 * 4;   // 36864+36864+34816+2048 = 110592
    static bool attr_set = false;
    if (!attr_set) {
        cudaFuncSetAttribute(flash_mma,
                             cudaFuncAttributeMaxDynamicSharedMemorySize,
                             smem_bytes);
        attr_set = true;
    }

    h_kernel<<<NN / 8, 256>>>(X, W, b);
    apack_kernel<<<NN, 256>>>(A);
    flash_mma<<<SPLITS * 64, NT, smem_bytes>>>();
    merge_kernel<<<NN * DD / 256, 256>>>(Out);
}